// round 1
// baseline (speedup 1.0000x reference)
#include <cuda_runtime.h>
#include <cuda_bf16.h>

// PositionalEncoding: out[pos, 2i] = sin(pos * 10000^{-2i/1024})
//                     out[pos, 2i+1] = cos(...)
// seq_len = out_size / 1024. Input X is unused (shape-only).
//
// Strategy: thread = pair index i (0..511), block = one full row of pairs,
// grid-stride over pos rows. powf hoisted per-thread. float2 stores fully
// coalesced. Pure store-bound kernel; accurate sincosf for correctness at
// large angles (theta up to ~8191 rad).

#define D_MODEL 1024
#define D_HALF  (D_MODEL / 2)

__global__ __launch_bounds__(D_HALF, 4)
void pe_kernel(float2* __restrict__ out, int seq_len) {
    const int i = threadIdx.x;                 // pair index 0..511
    // inverse frequency: 10000^{-2i/1024}
    const float w = powf(10000.0f, -(float)(2 * i) * (1.0f / (float)D_MODEL));

    for (int pos = blockIdx.x; pos < seq_len; pos += gridDim.x) {
        float theta = (float)pos * w;
        float s, c;
        sincosf(theta, &s, &c);
        out[(size_t)pos * D_HALF + i] = make_float2(s, c);
    }
}

extern "C" void kernel_launch(void* const* d_in, const int* in_sizes, int n_in,
                              void* d_out, int out_size) {
    (void)d_in; (void)in_sizes; (void)n_in;
    const int seq_len = out_size / D_MODEL;    // 8192
    float2* out = (float2*)d_out;

    // 148 SMs x 4 blocks of 512 threads = 592 blocks -> single wave,
    // grid-stride loop covers all rows.
    int grid = 148 * 4;
    if (grid > seq_len) grid = seq_len;
    pe_kernel<<<grid, D_HALF>>>(out, seq_len);
}